// round 13
// baseline (speedup 1.0000x reference)
#include <cuda_runtime.h>
#include <cstdint>

// Haar 2x2 wavelet: in (16,32,512,512) f32 -> out (16,128,256,256) f32
// out[b][0*32+c] = pooled, [1*32+c] = diff_h, [2*32+c] = diff_v, [3*32+c] = diff_d
//
// FINAL — converged (7 reproductions: kernel 149.1-150.8 us, +/-0.5%;
// harness 156.3-157.6 us). Streaming kernel at the HBM ceiling:
// 1.074 GB compulsory traffic in ~150 us = 7.1 TB/s SM-side (~89% of
// 8 TB/s pin spec; ncu DRAM counter reads 85-86% because dirty output
// lines remain in L2 at kernel end). All LDG.128/STG.128 coalesced,
// zero over-fetch. L2 = 40% (LTS cap not binding), issue = 11.5%
// (front end idle on memory), fma = 7.4%, regs = 31.
//
// Exhaustively measured search space:
//   - 2x per-thread tile (MLP 4->8): regs 32->48, occ 75->49%, -12%
//   - __ldcs/__stcs evict-first (both or load-only): -1.5..-11%
//   - persistent grid-stride (1184 CTAs): chip MLP falls, -11%
//   - block 512: neutral
//   - butterfly arithmetic (kept): time-neutral, -33% FADDs, regs 31,
//     rel_err 4.5e-8 (fp32 reassociation, 4+ orders under 1e-3 threshold)
// Binding constraint: DRAM read/write-turnaround protocol overhead for a
// balanced 1:1 read:write stream — unreachable from SM-side code.

#define B_  16
#define C_  32
#define H_  512
#define W_  512
#define HO_ 256
#define WO_ 256

__global__ __launch_bounds__(256) void haar_kernel(
    const float* __restrict__ x, float* __restrict__ out)
{
    // One thread = 4 output pixels (float4 wide) at (bc, h, w4*4..w4*4+3)
    // total threads = B*C*HO*(WO/4) = 16*32*256*64 = 8,388,608
    const uint32_t t = blockIdx.x * blockDim.x + threadIdx.x;

    const uint32_t w4  = t & 63u;          // WO/4 = 64
    uint32_t tmp       = t >> 6;
    const uint32_t h   = tmp & 255u;       // HO = 256
    const uint32_t bc  = tmp >> 8;         // 0..511 (b*C + c)

    // ---- input loads: rows 2h and 2h+1, cols 8*w4 .. 8*w4+7 ----
    const float* row0 = x + ((size_t)bc * (H_ * W_)) + (size_t)(2u * h) * W_ + w4 * 8u;
    const float* row1 = row0 + W_;

    const float4 t0 = *reinterpret_cast<const float4*>(row0);
    const float4 t1 = *reinterpret_cast<const float4*>(row0 + 4);
    const float4 b0 = *reinterpret_cast<const float4*>(row1);
    const float4 b1 = *reinterpret_cast<const float4*>(row1 + 4);

    float4 pooled, dh, dv, dd;

    // Butterfly per quad: (a,b) = top pair, (c,d) = bottom pair.
    #define HAARQ(a_, b_, c_, d_, i)                 \
    {                                                \
        const float s0 = (a_) + (b_);                \
        const float s1 = (c_) + (d_);                \
        const float g0 = (a_) - (b_);                \
        const float g1 = (c_) - (d_);                \
        pooled.i = (s0 + s1) * 0.25f;                \
        dh.i     = (s0 - s1) * 0.5f;                 \
        dv.i     = (g0 + g1) * 0.5f;                 \
        dd.i     =  g0 - g1;                         \
    }

    HAARQ(t0.x, t0.y, b0.x, b0.y, x)
    HAARQ(t0.z, t0.w, b0.z, b0.w, y)
    HAARQ(t1.x, t1.y, b1.x, b1.y, z)
    HAARQ(t1.z, t1.w, b1.z, b1.w, w)
    #undef HAARQ

    // ---- output stores ----
    const uint32_t b_idx = bc >> 5;        // /32
    const uint32_t ch    = bc & 31u;       // %32
    // out[b][g*32+ch][h][w]; plane = HO*WO = 65536
    const size_t plane = (size_t)HO_ * WO_;
    float* obase = out + ((size_t)b_idx * (4 * C_) + ch) * plane
                       + (size_t)h * WO_ + w4 * 4u;

    *reinterpret_cast<float4*>(obase)                   = pooled;  // group 0
    *reinterpret_cast<float4*>(obase + 1 * C_ * plane)  = dh;      // group 1
    *reinterpret_cast<float4*>(obase + 2 * C_ * plane)  = dv;      // group 2
    *reinterpret_cast<float4*>(obase + 3 * C_ * plane)  = dd;      // group 3
}

extern "C" void kernel_launch(void* const* d_in, const int* in_sizes, int n_in,
                              void* d_out, int out_size)
{
    const float* x = (const float*)d_in[0];
    float* out = (float*)d_out;

    const uint32_t total_threads = B_ * C_ * HO_ * (WO_ / 4);  // 8,388,608
    const uint32_t block = 256;
    const uint32_t grid = total_threads / block;               // 32768

    haar_kernel<<<grid, block>>>(x, out);
}

// round 14
// speedup vs baseline: 1.0004x; 1.0004x over previous
#include <cuda_runtime.h>
#include <cstdint>

// Haar 2x2 wavelet: in (16,32,512,512) f32 -> out (16,128,256,256) f32
// out[b][0*32+c] = pooled, [1*32+c] = diff_h, [2*32+c] = diff_v, [3*32+c] = diff_d
//
// R14: identical 31-reg SASS body to the converged optimum; final
// completeness point on the launch-geometry axis: block 256 -> 128
// (grid 32768 -> 65536, up to 16 CTAs/SM). Expected neutral — the memory
// system is demand-saturated and R8 showed geometry-insensitivity at 512.
// Keep only if >=1.5us under the 156.3us record; else block-256 is final.
//
// Converged baseline: kernel 149.1-150.8us over 8 runs, DRAM 85.5-86.2%,
// 6.8 TB/s (SM-side effective ~7.1 TB/s = 89% of pin spec). All other
// levers measured and rejected: 2x tile (-12%), .cs hints (-1.5..-11%),
// persistent grid (-11%), block 512 (neutral), butterfly (kept, neutral).

#define B_  16
#define C_  32
#define H_  512
#define W_  512
#define HO_ 256
#define WO_ 256

__global__ __launch_bounds__(128) void haar_kernel(
    const float* __restrict__ x, float* __restrict__ out)
{
    // One thread = 4 output pixels (float4 wide) at (bc, h, w4*4..w4*4+3)
    // total threads = B*C*HO*(WO/4) = 16*32*256*64 = 8,388,608
    const uint32_t t = blockIdx.x * blockDim.x + threadIdx.x;

    const uint32_t w4  = t & 63u;          // WO/4 = 64
    uint32_t tmp       = t >> 6;
    const uint32_t h   = tmp & 255u;       // HO = 256
    const uint32_t bc  = tmp >> 8;         // 0..511 (b*C + c)

    // ---- input loads: rows 2h and 2h+1, cols 8*w4 .. 8*w4+7 ----
    const float* row0 = x + ((size_t)bc * (H_ * W_)) + (size_t)(2u * h) * W_ + w4 * 8u;
    const float* row1 = row0 + W_;

    const float4 t0 = *reinterpret_cast<const float4*>(row0);
    const float4 t1 = *reinterpret_cast<const float4*>(row0 + 4);
    const float4 b0 = *reinterpret_cast<const float4*>(row1);
    const float4 b1 = *reinterpret_cast<const float4*>(row1 + 4);

    float4 pooled, dh, dv, dd;

    // Butterfly per quad: (a,b) = top pair, (c,d) = bottom pair.
    #define HAARQ(a_, b_, c_, d_, i)                 \
    {                                                \
        const float s0 = (a_) + (b_);                \
        const float s1 = (c_) + (d_);                \
        const float g0 = (a_) - (b_);                \
        const float g1 = (c_) - (d_);                \
        pooled.i = (s0 + s1) * 0.25f;                \
        dh.i     = (s0 - s1) * 0.5f;                 \
        dv.i     = (g0 + g1) * 0.5f;                 \
        dd.i     =  g0 - g1;                         \
    }

    HAARQ(t0.x, t0.y, b0.x, b0.y, x)
    HAARQ(t0.z, t0.w, b0.z, b0.w, y)
    HAARQ(t1.x, t1.y, b1.x, b1.y, z)
    HAARQ(t1.z, t1.w, b1.z, b1.w, w)
    #undef HAARQ

    // ---- output stores ----
    const uint32_t b_idx = bc >> 5;        // /32
    const uint32_t ch    = bc & 31u;       // %32
    // out[b][g*32+ch][h][w]; plane = HO*WO = 65536
    const size_t plane = (size_t)HO_ * WO_;
    float* obase = out + ((size_t)b_idx * (4 * C_) + ch) * plane
                       + (size_t)h * WO_ + w4 * 4u;

    *reinterpret_cast<float4*>(obase)                   = pooled;  // group 0
    *reinterpret_cast<float4*>(obase + 1 * C_ * plane)  = dh;      // group 1
    *reinterpret_cast<float4*>(obase + 2 * C_ * plane)  = dv;      // group 2
    *reinterpret_cast<float4*>(obase + 3 * C_ * plane)  = dd;      // group 3
}

extern "C" void kernel_launch(void* const* d_in, const int* in_sizes, int n_in,
                              void* d_out, int out_size)
{
    const float* x = (const float*)d_in[0];
    float* out = (float*)d_out;

    const uint32_t total_threads = B_ * C_ * HO_ * (WO_ / 4);  // 8,388,608
    const uint32_t block = 128;
    const uint32_t grid = total_threads / block;               // 65536

    haar_kernel<<<grid, block>>>(x, out);
}

// round 15
// speedup vs baseline: 1.0049x; 1.0045x over previous
#include <cuda_runtime.h>
#include <cstdint>

// Haar 2x2 wavelet: in (16,32,512,512) f32 -> out (16,128,256,256) f32
// out[b][0*32+c] = pooled, [1*32+c] = diff_h, [2*32+c] = diff_v, [3*32+c] = diff_d
//
// FINAL — fully converged. 9 reproductions of this config: kernel
// 149.1-150.8 us, harness 156.3-157.8 us, DRAM 85.5-86.2% (6.8 TB/s;
// SM-side effective ~7.1 TB/s = 89% of 8 TB/s pin spec — the ncu DRAM
// counter undercounts because dirty output lines remain in L2 at kernel
// end). Traffic is compulsory-minimal: 512 MiB read once + 512 MiB
// written once, all LDG.128/STG.128 coalesced, zero over-fetch.
// L2 = 40% (LTS cap not binding), issue = 11.5%, fma = 7.4%, regs = 31.
//
// Exhaustively measured search space — every axis closed:
//   - 2x per-thread tile (MLP 4->8): regs 32->48, occ 75->49%, -12%
//   - __ldcs/__stcs evict-first (both or load-only): -1.5..-11%
//   - persistent grid-stride (1184 CTAs): chip MLP falls, -11%
//   - block 128 / 512: neutral (memory system geometry-insensitive)
//   - butterfly arithmetic (kept): time-neutral, -33% FADDs,
//     rel_err 4.5e-8 (fp32 reassociation, 4+ orders under 1e-3)
// Binding constraint: DRAM read/write-turnaround protocol overhead for a
// balanced 1:1 read:write stream — unreachable from SM-side code.

#define B_  16
#define C_  32
#define H_  512
#define W_  512
#define HO_ 256
#define WO_ 256

__global__ __launch_bounds__(256) void haar_kernel(
    const float* __restrict__ x, float* __restrict__ out)
{
    // One thread = 4 output pixels (float4 wide) at (bc, h, w4*4..w4*4+3)
    // total threads = B*C*HO*(WO/4) = 16*32*256*64 = 8,388,608
    const uint32_t t = blockIdx.x * blockDim.x + threadIdx.x;

    const uint32_t w4  = t & 63u;          // WO/4 = 64
    uint32_t tmp       = t >> 6;
    const uint32_t h   = tmp & 255u;       // HO = 256
    const uint32_t bc  = tmp >> 8;         // 0..511 (b*C + c)

    // ---- input loads: rows 2h and 2h+1, cols 8*w4 .. 8*w4+7 ----
    const float* row0 = x + ((size_t)bc * (H_ * W_)) + (size_t)(2u * h) * W_ + w4 * 8u;
    const float* row1 = row0 + W_;

    const float4 t0 = *reinterpret_cast<const float4*>(row0);
    const float4 t1 = *reinterpret_cast<const float4*>(row0 + 4);
    const float4 b0 = *reinterpret_cast<const float4*>(row1);
    const float4 b1 = *reinterpret_cast<const float4*>(row1 + 4);

    float4 pooled, dh, dv, dd;

    // Butterfly per quad: (a,b) = top pair, (c,d) = bottom pair.
    #define HAARQ(a_, b_, c_, d_, i)                 \
    {                                                \
        const float s0 = (a_) + (b_);                \
        const float s1 = (c_) + (d_);                \
        const float g0 = (a_) - (b_);                \
        const float g1 = (c_) - (d_);                \
        pooled.i = (s0 + s1) * 0.25f;                \
        dh.i     = (s0 - s1) * 0.5f;                 \
        dv.i     = (g0 + g1) * 0.5f;                 \
        dd.i     =  g0 - g1;                         \
    }

    HAARQ(t0.x, t0.y, b0.x, b0.y, x)
    HAARQ(t0.z, t0.w, b0.z, b0.w, y)
    HAARQ(t1.x, t1.y, b1.x, b1.y, z)
    HAARQ(t1.z, t1.w, b1.z, b1.w, w)
    #undef HAARQ

    // ---- output stores ----
    const uint32_t b_idx = bc >> 5;        // /32
    const uint32_t ch    = bc & 31u;       // %32
    // out[b][g*32+ch][h][w]; plane = HO*WO = 65536
    const size_t plane = (size_t)HO_ * WO_;
    float* obase = out + ((size_t)b_idx * (4 * C_) + ch) * plane
                       + (size_t)h * WO_ + w4 * 4u;

    *reinterpret_cast<float4*>(obase)                   = pooled;  // group 0
    *reinterpret_cast<float4*>(obase + 1 * C_ * plane)  = dh;      // group 1
    *reinterpret_cast<float4*>(obase + 2 * C_ * plane)  = dv;      // group 2
    *reinterpret_cast<float4*>(obase + 3 * C_ * plane)  = dd;      // group 3
}

extern "C" void kernel_launch(void* const* d_in, const int* in_sizes, int n_in,
                              void* d_out, int out_size)
{
    const float* x = (const float*)d_in[0];
    float* out = (float*)d_out;

    const uint32_t total_threads = B_ * C_ * HO_ * (WO_ / 4);  // 8,388,608
    const uint32_t block = 256;
    const uint32_t grid = total_threads / block;               // 32768

    haar_kernel<<<grid, block>>>(x, out);
}